// round 1
// baseline (speedup 1.0000x reference)
#include <cuda_runtime.h>
#include <cuda_bf16.h>

// Problem constants (fixed shapes)
#define BB 8
#define LL 512
#define DD 1024
#define NN 8192
#define GD 64
#define KK 256          // kept tokens per batch (= L - r_step, r_step = 256)
#define TLIST 32        // top-T candidate list per row

// ---------------- scratch (device globals; no allocation allowed) ----------------
__device__ float               g_gu[BB * LL * GD];     // normalized group embeddings
__device__ float               g_gn[BB * LL];          // raw norms (merge weights)
__device__ float               g_sim[BB * LL * LL];    // full sim matrix per batch
__device__ unsigned long long  g_lists[BB * LL * TLIST];
__device__ int4                g_pairs[BB * KK];       // {i, j, bits(wi), bits(wj)} per kept slot

// float -> totally-ordered ascending unsigned
__device__ __forceinline__ unsigned ordf(float f) {
    unsigned u = __float_as_uint(f);
    return (u & 0x80000000u) ? ~u : (u | 0x80000000u);
}

// =====================================================================
// K1: g = x @ W^T  (rows = flattened b*512+row), then gn, gu
// 128 blocks x 256 thr; 32-row tiles, K-chunks of 64
// =====================================================================
__global__ void __launch_bounds__(256) k_proj(const float* __restrict__ x,
                                              const float* __restrict__ W) {
    __shared__ float xs[32][65];   // stride 65 -> conflict free
    __shared__ float ws[64][66];   // even pad -> 8B aligned float2 reads
    __shared__ float gs[32][65];
    __shared__ float nrm[32];

    const int tid = threadIdx.x;
    const int rowBase = blockIdx.x * 32;       // 0..4095 flattened rows
    const int r = tid & 31, cg = tid >> 5;     // cg*8 .. cg*8+7 output cols

    float acc[8];
#pragma unroll
    for (int u = 0; u < 8; u++) acc[u] = 0.f;

    for (int kc = 0; kc < DD; kc += 64) {
#pragma unroll
        for (int it = 0; it < 2; it++) {       // xs: 512 float4
            int idx = tid + it * 256;
            int rr = idx >> 4, kk = (idx & 15) << 2;
            float4 v = *reinterpret_cast<const float4*>(
                &x[(size_t)(rowBase + rr) * DD + kc + kk]);
            xs[rr][kk] = v.x; xs[rr][kk + 1] = v.y; xs[rr][kk + 2] = v.z; xs[rr][kk + 3] = v.w;
        }
#pragma unroll
        for (int it = 0; it < 4; it++) {       // ws: 1024 float4
            int idx = tid + it * 256;
            int rr = idx >> 4, kk = (idx & 15) << 2;
            float4 v = *reinterpret_cast<const float4*>(
                &W[(size_t)rr * DD + kc + kk]);
            ws[rr][kk] = v.x; ws[rr][kk + 1] = v.y; ws[rr][kk + 2] = v.z; ws[rr][kk + 3] = v.w;
        }
        __syncthreads();
#pragma unroll 8
        for (int k = 0; k < 64; k += 2) {
            float x0 = xs[r][k], x1 = xs[r][k + 1];
#pragma unroll
            for (int u = 0; u < 8; u++) {
                float2 w = *reinterpret_cast<const float2*>(&ws[cg * 8 + u][k]);
                acc[u] = fmaf(x0, w.x, acc[u]);
                acc[u] = fmaf(x1, w.y, acc[u]);
            }
        }
        __syncthreads();
    }
#pragma unroll
    for (int u = 0; u < 8; u++) gs[r][cg * 8 + u] = acc[u];
    __syncthreads();
    if (tid < 32) {
        float s = 0.f;
#pragma unroll
        for (int c = 0; c < GD; c++) { float v = gs[tid][c]; s = fmaf(v, v, s); }
        float m = sqrtf(s);
        g_gn[rowBase + tid] = m;               // raw norm (merge weight)
        nrm[tid] = fmaxf(m, 1e-12f);
    }
    __syncthreads();
#pragma unroll
    for (int u = 0; u < 8; u++)
        g_gu[(size_t)(rowBase + r) * GD + cg * 8 + u] = gs[r][cg * 8 + u] / nrm[r];
}

// =====================================================================
// K2: sim = gu @ gu^T per batch; tiles 32x32, grid (16,16,8)
// =====================================================================
__global__ void __launch_bounds__(256) k_sim() {
    __shared__ float A[32][65], Bm[32][65];
    const int b = blockIdx.z, i0 = blockIdx.y * 32, j0 = blockIdx.x * 32;
    const int tid = threadIdx.x;
#pragma unroll
    for (int it = 0; it < 2; it++) {           // each tile: 512 float4
        int idx = tid + it * 256;
        int rr = idx >> 4, kk = (idx & 15) << 2;
        float4 v = *reinterpret_cast<const float4*>(
            &g_gu[((size_t)b * LL + i0 + rr) * GD + kk]);
        A[rr][kk] = v.x; A[rr][kk + 1] = v.y; A[rr][kk + 2] = v.z; A[rr][kk + 3] = v.w;
        float4 w = *reinterpret_cast<const float4*>(
            &g_gu[((size_t)b * LL + j0 + rr) * GD + kk]);
        Bm[rr][kk] = w.x; Bm[rr][kk + 1] = w.y; Bm[rr][kk + 2] = w.z; Bm[rr][kk + 3] = w.w;
    }
    __syncthreads();
    const int c = tid & 31, r0 = (tid >> 5) * 4;   // 4 rows per thread, contiguous cols
    float acc[4] = {0.f, 0.f, 0.f, 0.f};
#pragma unroll
    for (int k = 0; k < GD; k++) {
        float bv = Bm[c][k];
#pragma unroll
        for (int u = 0; u < 4; u++) acc[u] = fmaf(A[r0 + u][k], bv, acc[u]);
    }
#pragma unroll
    for (int u = 0; u < 4; u++)
        g_sim[((size_t)b * LL + i0 + r0 + u) * LL + j0 + c] = acc[u];  // coalesced
}

// =====================================================================
// K3: per row, top-32 candidate keys (ascending key = descending sim, tie (i,j))
// block = 8 warps, warp per row; 512 blocks
// =====================================================================
__global__ void __launch_bounds__(256) k_lists() {
    const int warp = threadIdx.x >> 5, lane = threadIdx.x & 31;
    const int rr = blockIdx.x * 8 + warp;      // 0..4095
    const int i = rr & (LL - 1);
    const float* srow = &g_sim[(size_t)rr * LL];
    unsigned long long keys[16];
#pragma unroll
    for (int q = 0; q < 4; q++) {
        float4 v = *reinterpret_cast<const float4*>(&srow[(lane + q * 32) * 4]);
        float f[4] = {v.x, v.y, v.z, v.w};
#pragma unroll
        for (int e = 0; e < 4; e++) {
            int cc = (lane + q * 32) * 4 + e;
            unsigned long long kk;
            if (cc == i) kk = ~0ULL;
            else {
                int a = min(i, cc), d = max(i, cc);
                kk = ((unsigned long long)(~ordf(f[e])) << 18) |
                     (unsigned)((a << 9) | d);
            }
            keys[q * 4 + e] = kk;
        }
    }
    unsigned long long* out = &g_lists[(size_t)rr * TLIST];
    for (int t = 0; t < TLIST; t++) {
        unsigned long long m = ~0ULL;
#pragma unroll
        for (int q = 0; q < 16; q++) m = keys[q] < m ? keys[q] : m;
#pragma unroll
        for (int o = 16; o; o >>= 1) {
            unsigned long long o2 = __shfl_xor_sync(0xffffffffu, m, o);
            m = o2 < m ? o2 : m;
        }
        if (lane == 0) out[t] = m;
#pragma unroll
        for (int q = 0; q < 16; q++) if (keys[q] == m) keys[q] = ~0ULL;
    }
}

// =====================================================================
// K4: greedy matching, one block per batch; warp 0 runs the sequential loop
// lazy row-minima in registers (16 rows per lane), lists in smem
// =====================================================================
__global__ void __launch_bounds__(256) k_greedy() {
    extern __shared__ unsigned long long sl[];   // 512*32 keys = 128 KB
    __shared__ int sel_i[KK], sel_j[KK];
    __shared__ unsigned ibits[16];

    const int b = blockIdx.x, tid = threadIdx.x;
    {   // copy this batch's lists to smem (8192 float4)
        const float4* srcp = reinterpret_cast<const float4*>(&g_lists[(size_t)b * LL * TLIST]);
        float4* dstp = reinterpret_cast<float4*>(sl);
#pragma unroll
        for (int q = 0; q < 32; q++) dstp[tid + q * 256] = srcp[tid + q * 256];
    }
    if (tid < 16) ibits[tid] = 0u;
    __syncthreads();

    if (tid < 32) {
        const int lane = tid;
        unsigned long long bk[16];
        unsigned ub[16];
        int hd[16];
#pragma unroll
        for (int t = 0; t < 16; t++) {
            bk[t] = sl[(size_t)(32 * t + lane) * TLIST];
            ub[t] = 0u; hd[t] = 0;
        }
        for (int iter = 0; iter < KK; iter++) {
            unsigned long long m = ~0ULL;
#pragma unroll
            for (int t = 0; t < 16; t++) m = bk[t] < m ? bk[t] : m;
#pragma unroll
            for (int o = 16; o; o >>= 1) {
                unsigned long long o2 = __shfl_xor_sync(0xffffffffu, m, o);
                m = o2 < m ? o2 : m;
            }
            const int i = (int)((m >> 9) & 511), j = (int)(m & 511);
            if (lane == 0) { sel_i[iter] = i; sel_j[iter] = j; }
            ub[i >> 5] |= 1u << (i & 31);
            ub[j >> 5] |= 1u << (j & 31);

            unsigned pend = 0u;
#pragma unroll
            for (int t = 0; t < 16; t++) {
                if (bk[t] == ~0ULL) continue;
                const int r = 32 * t + lane;
                if (r == i || r == j) { bk[t] = ~0ULL; continue; }
                int pmin = (int)((bk[t] >> 9) & 511), pmax = (int)(bk[t] & 511);
                int p = pmin ^ pmax ^ r;
                if (p == i || p == j) {          // cached partner died -> advance
                    int h = hd[t];
                    unsigned long long nb = ~0ULL;
                    while (++h < TLIST) {
                        unsigned long long e = sl[(size_t)r * TLIST + h];
                        int q2 = ((int)((e >> 9) & 511)) ^ ((int)(e & 511)) ^ r;
                        if (!((ub[q2 >> 5] >> (q2 & 31)) & 1u)) { nb = e; break; }
                    }
                    hd[t] = h; bk[t] = nb;
                    if (nb == ~0ULL) pend |= 1u << t;
                }
            }
            // cooperative fallback rescans (row's top-32 exhausted)
            unsigned any = __ballot_sync(0xffffffffu, pend != 0u);
            while (any) {
                int srcl = __ffs(any) - 1; any &= any - 1;
                unsigned pm = __shfl_sync(0xffffffffu, pend, srcl);
                while (pm) {
                    int t = __ffs(pm) - 1; pm &= pm - 1;
                    int r = 32 * t + srcl;
                    unsigned long long best = ~0ULL;
                    const float* srow = &g_sim[((size_t)b * LL + r) * LL];
                    for (int cc = lane; cc < LL; cc += 32) {
                        if (cc == r) continue;
                        if ((ub[cc >> 5] >> (cc & 31)) & 1u) continue;
                        int a = cc < r ? cc : r, d = cc < r ? r : cc;
                        unsigned long long kk =
                            ((unsigned long long)(~ordf(srow[cc])) << 18) |
                            (unsigned)((a << 9) | d);
                        best = kk < best ? kk : best;
                    }
#pragma unroll
                    for (int o = 16; o; o >>= 1) {
                        unsigned long long o2 = __shfl_xor_sync(0xffffffffu, best, o);
                        best = o2 < best ? o2 : best;
                    }
                    if (lane == srcl) bk[t] = best;
                }
            }
        }
    }
    __syncthreads();
    // rank kept tokens (ascending i) and emit pair records
    atomicOr(&ibits[sel_i[tid] >> 5], 1u << (sel_i[tid] & 31));
    __syncthreads();
    {
        int i = sel_i[tid], j = sel_j[tid];
        int rank = 0;
        for (int w2 = 0; w2 < (i >> 5); w2++) rank += __popc(ibits[w2]);
        rank += __popc(ibits[i >> 5] & ((1u << (i & 31)) - 1u));
        float wi = g_gn[b * LL + i], wj = g_gn[b * LL + j];
        g_pairs[b * KK + rank] = make_int4(i, j, __float_as_int(wi), __float_as_int(wj));
    }
}

// =====================================================================
// K5: merge outputs — xm then sm (HBM-bound, float4 everywhere)
// 2048 blocks (one per output row), 256 threads
// =====================================================================
__global__ void __launch_bounds__(256) k_merge(const float* __restrict__ x,
                                               const float* __restrict__ src,
                                               float* __restrict__ out) {
    const int blk = blockIdx.x;
    const int b = blk >> 8, slot = blk & 255;
    int4 p = g_pairs[blk];
    const int i = p.x, j = p.y;
    const float wi = __int_as_float(p.z), wj = __int_as_float(p.w);
    const float tot = wi + wj + 1e-8f;
    const float ai = wi / tot, aj = wj / tot;
    const int t = threadIdx.x;

    const float4* xi = reinterpret_cast<const float4*>(&x[((size_t)b * LL + i) * DD]);
    const float4* xj = reinterpret_cast<const float4*>(&x[((size_t)b * LL + j) * DD]);
    float4* xo = reinterpret_cast<float4*>(&out[((size_t)b * KK + slot) * DD]);
    {
        float4 a = xi[t], c = xj[t], o;
        o.x = fmaf(ai, a.x, aj * c.x);
        o.y = fmaf(ai, a.y, aj * c.y);
        o.z = fmaf(ai, a.z, aj * c.z);
        o.w = fmaf(ai, a.w, aj * c.w);
        xo[t] = o;
    }
    const float4* si = reinterpret_cast<const float4*>(&src[((size_t)b * LL + i) * NN]);
    const float4* sj = reinterpret_cast<const float4*>(&src[((size_t)b * LL + j) * NN]);
    float4* so = reinterpret_cast<float4*>(
        &out[(size_t)BB * KK * DD + ((size_t)b * KK + slot) * NN]);
#pragma unroll
    for (int q = 0; q < 8; q++) {
        int idx = t + q * 256;
        float4 a = si[idx], c = sj[idx], o;
        o.x = a.x + c.x; o.y = a.y + c.y; o.z = a.z + c.z; o.w = a.w + c.w;
        so[idx] = o;
    }
}

// =====================================================================
extern "C" void kernel_launch(void* const* d_in, const int* in_sizes, int n_in,
                              void* d_out, int out_size) {
    const float* x = nullptr;
    const float* src = nullptr;
    const float* W = nullptr;
    for (int k = 0; k < n_in; k++) {
        if (in_sizes[k] == BB * LL * DD) x = (const float*)d_in[k];
        else if (in_sizes[k] == BB * LL * NN) src = (const float*)d_in[k];
        else if (in_sizes[k] == GD * DD) W = (const float*)d_in[k];
    }
    float* out = (float*)d_out;

    cudaFuncSetAttribute(k_greedy, cudaFuncAttributeMaxDynamicSharedMemorySize,
                         LL * TLIST * (int)sizeof(unsigned long long));

    k_proj<<<(BB * LL) / 32, 256>>>(x, W);
    dim3 gsim(16, 16, BB);
    k_sim<<<gsim, 256>>>();
    k_lists<<<(BB * LL) / 8, 256>>>();
    k_greedy<<<BB, 256, LL * TLIST * sizeof(unsigned long long)>>>();
    k_merge<<<BB * KK, 256>>>(x, src, out);
}

// round 2
// speedup vs baseline: 4.2229x; 4.2229x over previous
#include <cuda_runtime.h>
#include <cuda_bf16.h>

// Problem constants (fixed shapes)
#define BB 8
#define LL 512
#define DD 1024
#define NN 8192
#define GD 64
#define KK 256          // kept tokens per batch (= L - r_step, r_step = 256)

// ---------------- scratch (device globals; no allocation allowed) ----------------
__device__ float               g_gu[BB * LL * GD];     // normalized group embeddings
__device__ float               g_gn[BB * LL];          // raw norms (merge weights)
__device__ float               g_sim[BB * LL * LL];    // full sim matrix per batch
__device__ unsigned long long  g_best[BB * LL];        // initial best-available key per row
__device__ int4                g_pairs[BB * KK];       // {i, j, bits(wi), bits(wj)} per kept slot

// float -> totally-ordered ascending unsigned
__device__ __forceinline__ unsigned ordf(float f) {
    unsigned u = __float_as_uint(f);
    return (u & 0x80000000u) ? ~u : (u | 0x80000000u);
}

// build key: ascending key == descending sim, tie-break (i,j) lexicographic
__device__ __forceinline__ unsigned long long mkkey(float s, int r, int cc) {
    int a = min(r, cc), d = max(r, cc);
    return ((unsigned long long)(~ordf(s)) << 18) | (unsigned)((a << 9) | d);
}

// =====================================================================
// K1: g = x @ W^T  (rows = flattened b*512+row), then gn, gu
// 128 blocks x 256 thr; 32-row tiles, K-chunks of 64
// =====================================================================
__global__ void __launch_bounds__(256) k_proj(const float* __restrict__ x,
                                              const float* __restrict__ W) {
    __shared__ float xs[32][65];   // stride 65 -> conflict free
    __shared__ float ws[64][66];   // even pad -> 8B aligned float2 reads
    __shared__ float gs[32][65];
    __shared__ float nrm[32];

    const int tid = threadIdx.x;
    const int rowBase = blockIdx.x * 32;       // 0..4095 flattened rows
    const int r = tid & 31, cg = tid >> 5;     // cg*8 .. cg*8+7 output cols

    float acc[8];
#pragma unroll
    for (int u = 0; u < 8; u++) acc[u] = 0.f;

    for (int kc = 0; kc < DD; kc += 64) {
#pragma unroll
        for (int it = 0; it < 2; it++) {       // xs: 512 float4
            int idx = tid + it * 256;
            int rr = idx >> 4, kk = (idx & 15) << 2;
            float4 v = *reinterpret_cast<const float4*>(
                &x[(size_t)(rowBase + rr) * DD + kc + kk]);
            xs[rr][kk] = v.x; xs[rr][kk + 1] = v.y; xs[rr][kk + 2] = v.z; xs[rr][kk + 3] = v.w;
        }
#pragma unroll
        for (int it = 0; it < 4; it++) {       // ws: 1024 float4
            int idx = tid + it * 256;
            int rr = idx >> 4, kk = (idx & 15) << 2;
            float4 v = *reinterpret_cast<const float4*>(
                &W[(size_t)rr * DD + kc + kk]);
            ws[rr][kk] = v.x; ws[rr][kk + 1] = v.y; ws[rr][kk + 2] = v.z; ws[rr][kk + 3] = v.w;
        }
        __syncthreads();
#pragma unroll 8
        for (int k = 0; k < 64; k += 2) {
            float x0 = xs[r][k], x1 = xs[r][k + 1];
#pragma unroll
            for (int u = 0; u < 8; u++) {
                float2 w = *reinterpret_cast<const float2*>(&ws[cg * 8 + u][k]);
                acc[u] = fmaf(x0, w.x, acc[u]);
                acc[u] = fmaf(x1, w.y, acc[u]);
            }
        }
        __syncthreads();
    }
#pragma unroll
    for (int u = 0; u < 8; u++) gs[r][cg * 8 + u] = acc[u];
    __syncthreads();
    if (tid < 32) {
        float s = 0.f;
#pragma unroll
        for (int c = 0; c < GD; c++) { float v = gs[tid][c]; s = fmaf(v, v, s); }
        float m = sqrtf(s);
        g_gn[rowBase + tid] = m;               // raw norm (merge weight)
        nrm[tid] = fmaxf(m, 1e-12f);
    }
    __syncthreads();
#pragma unroll
    for (int u = 0; u < 8; u++)
        g_gu[(size_t)(rowBase + r) * GD + cg * 8 + u] = gs[r][cg * 8 + u] / nrm[r];
}

// =====================================================================
// K2: sim = gu @ gu^T per batch; tiles 32x32, grid (16,16,8)
// NOTE: sim[i][j] and sim[j][i] are computed with identical k-ordering
// -> bitwise symmetric, required for the mutual-best matching.
// =====================================================================
__global__ void __launch_bounds__(256) k_sim() {
    __shared__ float A[32][65], Bm[32][65];
    const int b = blockIdx.z, i0 = blockIdx.y * 32, j0 = blockIdx.x * 32;
    const int tid = threadIdx.x;
#pragma unroll
    for (int it = 0; it < 2; it++) {           // each tile: 512 float4
        int idx = tid + it * 256;
        int rr = idx >> 4, kk = (idx & 15) << 2;
        float4 v = *reinterpret_cast<const float4*>(
            &g_gu[((size_t)b * LL + i0 + rr) * GD + kk]);
        A[rr][kk] = v.x; A[rr][kk + 1] = v.y; A[rr][kk + 2] = v.z; A[rr][kk + 3] = v.w;
        float4 w = *reinterpret_cast<const float4*>(
            &g_gu[((size_t)b * LL + j0 + rr) * GD + kk]);
        Bm[rr][kk] = w.x; Bm[rr][kk + 1] = w.y; Bm[rr][kk + 2] = w.z; Bm[rr][kk + 3] = w.w;
    }
    __syncthreads();
    const int c = tid & 31, r0 = (tid >> 5) * 4;   // 4 rows per thread, contiguous cols
    float acc[4] = {0.f, 0.f, 0.f, 0.f};
#pragma unroll
    for (int k = 0; k < GD; k++) {
        float bv = Bm[c][k];
#pragma unroll
        for (int u = 0; u < 4; u++) acc[u] = fmaf(A[r0 + u][k], bv, acc[u]);
    }
#pragma unroll
    for (int u = 0; u < 4; u++)
        g_sim[((size_t)b * LL + i0 + r0 + u) * LL + j0 + c] = acc[u];  // coalesced
}

// =====================================================================
// K3: initial best-available key per row (full chip, warp per row)
// grid = BB*LL/8 blocks, 8 warps each
// =====================================================================
__global__ void __launch_bounds__(256) k_binit() {
    const int warp = threadIdx.x >> 5, lane = threadIdx.x & 31;
    const int rr = blockIdx.x * 8 + warp;      // 0..4095 flattened
    const int r = rr & (LL - 1);
    const float4* row4 = reinterpret_cast<const float4*>(&g_sim[(size_t)rr * LL]);
    unsigned long long m = ~0ULL;
#pragma unroll
    for (int q = 0; q < 4; q++) {
        float4 v = row4[lane + q * 32];
        float f[4] = {v.x, v.y, v.z, v.w};
        int cbase = (lane + q * 32) * 4;
#pragma unroll
        for (int e = 0; e < 4; e++) {
            int cc = cbase + e;
            if (cc == r) continue;
            unsigned long long kk = mkkey(f[e], r, cc);
            m = kk < m ? kk : m;
        }
    }
#pragma unroll
    for (int o = 16; o; o >>= 1) {
        unsigned long long o2 = __shfl_xor_sync(0xffffffffu, m, o);
        m = o2 < m ? o2 : m;
    }
    if (lane == 0) g_best[rr] = m;
}

// =====================================================================
// K4: greedy matching via iterated mutual-best (locally dominant) rounds.
// One block per batch, 512 threads (16 warps).
// Identical selected SET as sequential greedy (distinct keys).
// =====================================================================
__global__ void __launch_bounds__(512) k_greedy() {
    __shared__ unsigned long long best[LL];    // per-row best-available key
    __shared__ unsigned used[16];
    __shared__ short qrows[LL];                // rows needing rescan this round
    __shared__ int qn, nsel;
    __shared__ short sel_i[KK], sel_j[KK];
    __shared__ unsigned ibits[16];

    const int b = blockIdx.x, tid = threadIdx.x;
    const int warp = tid >> 5, lane = tid & 31;
    const float* simb = &g_sim[(size_t)b * LL * LL];

    if (tid < LL) best[tid] = g_best[b * LL + tid];
    if (tid < 16) { used[tid] = 0u; ibits[tid] = 0u; }
    if (tid == 0) { nsel = 0; qn = 0; }
    __syncthreads();

    while (true) {
        // --- mutual-best selection (thread per row) ---
        {
            const int r = tid;
            if (!((used[r >> 5] >> (r & 31)) & 1u)) {
                unsigned long long k = best[r];
                int a = (int)((k >> 9) & 511), d = (int)(k & 511);
                if (r == a && best[d] == k) {      // mutual; select once (r = min endpoint)
                    int s = atomicAdd(&nsel, 1);
                    sel_i[s] = (short)a; sel_j[s] = (short)d;
                    atomicOr(&used[a >> 5], 1u << (a & 31));
                    atomicOr(&used[d >> 5], 1u << (d & 31));
                }
            }
        }
        __syncthreads();
        if (nsel >= KK) break;
        if (tid == 0) qn = 0;
        __syncthreads();
        // --- queue rows whose cached best just died ---
        {
            const int r = tid;
            if (!((used[r >> 5] >> (r & 31)) & 1u)) {
                unsigned long long k = best[r];
                int a = (int)((k >> 9) & 511), d = (int)(k & 511);
                int p = a ^ d ^ r;
                if ((used[p >> 5] >> (p & 31)) & 1u)
                    qrows[atomicAdd(&qn, 1)] = (short)r;
            }
        }
        __syncthreads();
        // --- warp-parallel rescans over L2-resident sim rows ---
        for (int qi = warp; qi < qn; qi += 16) {
            const int r = qrows[qi];
            const float4* row4 = reinterpret_cast<const float4*>(&simb[(size_t)r * LL]);
            float4 v[4];
#pragma unroll
            for (int q = 0; q < 4; q++) v[q] = row4[lane + q * 32];   // MLP=4
            unsigned long long m = ~0ULL;
#pragma unroll
            for (int q = 0; q < 4; q++) {
                float f[4] = {v[q].x, v[q].y, v[q].z, v[q].w};
                int cbase = (lane + q * 32) * 4;
#pragma unroll
                for (int e = 0; e < 4; e++) {
                    int cc = cbase + e;
                    if (cc == r) continue;
                    if ((used[cc >> 5] >> (cc & 31)) & 1u) continue;
                    unsigned long long kk = mkkey(f[e], r, cc);
                    m = kk < m ? kk : m;
                }
            }
#pragma unroll
            for (int o = 16; o; o >>= 1) {
                unsigned long long o2 = __shfl_xor_sync(0xffffffffu, m, o);
                m = o2 < m ? o2 : m;
            }
            if (lane == 0) best[r] = m;
        }
        __syncthreads();
    }

    // --- emit kept-slot pair records (rank = position of i among sorted i's) ---
    if (tid < KK) atomicOr(&ibits[sel_i[tid] >> 5], 1u << (sel_i[tid] & 31));
    __syncthreads();
    if (tid < KK) {
        int i = sel_i[tid], j = sel_j[tid];
        int rank = 0;
        for (int w2 = 0; w2 < (i >> 5); w2++) rank += __popc(ibits[w2]);
        rank += __popc(ibits[i >> 5] & ((1u << (i & 31)) - 1u));
        float wi = g_gn[b * LL + i], wj = g_gn[b * LL + j];
        g_pairs[b * KK + rank] = make_int4(i, j, __float_as_int(wi), __float_as_int(wj));
    }
}

// =====================================================================
// K5: merge outputs — xm then sm (HBM-bound, float4 everywhere)
// 2048 blocks (one per output row), 256 threads
// =====================================================================
__global__ void __launch_bounds__(256) k_merge(const float* __restrict__ x,
                                               const float* __restrict__ src,
                                               float* __restrict__ out) {
    const int blk = blockIdx.x;
    const int b = blk >> 8, slot = blk & 255;
    int4 p = g_pairs[blk];
    const int i = p.x, j = p.y;
    const float wi = __int_as_float(p.z), wj = __int_as_float(p.w);
    const float tot = wi + wj + 1e-8f;
    const float ai = wi / tot, aj = wj / tot;
    const int t = threadIdx.x;

    const float4* xi = reinterpret_cast<const float4*>(&x[((size_t)b * LL + i) * DD]);
    const float4* xj = reinterpret_cast<const float4*>(&x[((size_t)b * LL + j) * DD]);
    float4* xo = reinterpret_cast<float4*>(&out[((size_t)b * KK + slot) * DD]);
    {
        float4 a = xi[t], c = xj[t], o;
        o.x = fmaf(ai, a.x, aj * c.x);
        o.y = fmaf(ai, a.y, aj * c.y);
        o.z = fmaf(ai, a.z, aj * c.z);
        o.w = fmaf(ai, a.w, aj * c.w);
        xo[t] = o;
    }
    const float4* si = reinterpret_cast<const float4*>(&src[((size_t)b * LL + i) * NN]);
    const float4* sj = reinterpret_cast<const float4*>(&src[((size_t)b * LL + j) * NN]);
    float4* so = reinterpret_cast<float4*>(
        &out[(size_t)BB * KK * DD + ((size_t)b * KK + slot) * NN]);
#pragma unroll
    for (int q = 0; q < 8; q++) {
        int idx = t + q * 256;
        float4 a = si[idx], c = sj[idx], o;
        o.x = a.x + c.x; o.y = a.y + c.y; o.z = a.z + c.z; o.w = a.w + c.w;
        so[idx] = o;
    }
}

// =====================================================================
extern "C" void kernel_launch(void* const* d_in, const int* in_sizes, int n_in,
                              void* d_out, int out_size) {
    const float* x = nullptr;
    const float* src = nullptr;
    const float* W = nullptr;
    for (int k = 0; k < n_in; k++) {
        if (in_sizes[k] == BB * LL * DD) x = (const float*)d_in[k];
        else if (in_sizes[k] == BB * LL * NN) src = (const float*)d_in[k];
        else if (in_sizes[k] == GD * DD) W = (const float*)d_in[k];
    }
    float* out = (float*)d_out;

    k_proj<<<(BB * LL) / 32, 256>>>(x, W);
    dim3 gsim(16, 16, BB);
    k_sim<<<gsim, 256>>>();
    k_binit<<<(BB * LL) / 8, 256>>>();
    k_greedy<<<BB, 512>>>();
    k_merge<<<BB * KK, 256>>>(x, src, out);
}

// round 3
// speedup vs baseline: 4.4731x; 1.0592x over previous
#include <cuda_runtime.h>
#include <cuda_bf16.h>

// Problem constants (fixed shapes)
#define BB 8
#define LL 512
#define DD 1024
#define NN 8192
#define GD 64
#define KK 256          // kept tokens per batch (= L - r_step, r_step = 256)
#define TL 16           // top-K candidate list length per row
#define TLP 17          // padded smem stride (bank-conflict break)

// ---------------- scratch (device globals; no allocation allowed) ----------------
__device__ float               g_gu[BB * LL * GD];     // normalized group embeddings
__device__ float               g_gn[BB * LL];          // raw norms (merge weights)
__device__ float               g_sim[BB * LL * LL];    // full sim matrix per batch
__device__ unsigned long long  g_lists[BB * LL * TL];  // per-row top-16 keys
__device__ int4                g_pairs[BB * KK];       // {i, j, bits(wi), bits(wj)} per kept slot

// float -> totally-ordered ascending unsigned
__device__ __forceinline__ unsigned ordf(float f) {
    unsigned u = __float_as_uint(f);
    return (u & 0x80000000u) ? ~u : (u | 0x80000000u);
}

// build key: ascending key == descending sim, tie-break (i,j) lexicographic
__device__ __forceinline__ unsigned long long mkkey(float s, int r, int cc) {
    int a = min(r, cc), d = max(r, cc);
    return ((unsigned long long)(~ordf(s)) << 18) | (unsigned)((a << 9) | d);
}

// =====================================================================
// K1: g = x @ W^T  (rows = flattened b*512+row), then gn, gu
// =====================================================================
__global__ void __launch_bounds__(256) k_proj(const float* __restrict__ x,
                                              const float* __restrict__ W) {
    __shared__ float xs[32][65];
    __shared__ float ws[64][66];
    __shared__ float gs[32][65];
    __shared__ float nrm[32];

    const int tid = threadIdx.x;
    const int rowBase = blockIdx.x * 32;
    const int r = tid & 31, cg = tid >> 5;

    float acc[8];
#pragma unroll
    for (int u = 0; u < 8; u++) acc[u] = 0.f;

    for (int kc = 0; kc < DD; kc += 64) {
#pragma unroll
        for (int it = 0; it < 2; it++) {
            int idx = tid + it * 256;
            int rr = idx >> 4, kk = (idx & 15) << 2;
            float4 v = *reinterpret_cast<const float4*>(
                &x[(size_t)(rowBase + rr) * DD + kc + kk]);
            xs[rr][kk] = v.x; xs[rr][kk + 1] = v.y; xs[rr][kk + 2] = v.z; xs[rr][kk + 3] = v.w;
        }
#pragma unroll
        for (int it = 0; it < 4; it++) {
            int idx = tid + it * 256;
            int rr = idx >> 4, kk = (idx & 15) << 2;
            float4 v = *reinterpret_cast<const float4*>(
                &W[(size_t)rr * DD + kc + kk]);
            ws[rr][kk] = v.x; ws[rr][kk + 1] = v.y; ws[rr][kk + 2] = v.z; ws[rr][kk + 3] = v.w;
        }
        __syncthreads();
#pragma unroll 8
        for (int k = 0; k < 64; k += 2) {
            float x0 = xs[r][k], x1 = xs[r][k + 1];
#pragma unroll
            for (int u = 0; u < 8; u++) {
                float2 w = *reinterpret_cast<const float2*>(&ws[cg * 8 + u][k]);
                acc[u] = fmaf(x0, w.x, acc[u]);
                acc[u] = fmaf(x1, w.y, acc[u]);
            }
        }
        __syncthreads();
    }
#pragma unroll
    for (int u = 0; u < 8; u++) gs[r][cg * 8 + u] = acc[u];
    __syncthreads();
    if (tid < 32) {
        float s = 0.f;
#pragma unroll
        for (int c = 0; c < GD; c++) { float v = gs[tid][c]; s = fmaf(v, v, s); }
        float m = sqrtf(s);
        g_gn[rowBase + tid] = m;
        nrm[tid] = fmaxf(m, 1e-12f);
    }
    __syncthreads();
#pragma unroll
    for (int u = 0; u < 8; u++)
        g_gu[(size_t)(rowBase + r) * GD + cg * 8 + u] = gs[r][cg * 8 + u] / nrm[r];
}

// =====================================================================
// K2: sim = gu @ gu^T per batch; tiles 32x32, grid (16,16,8)
// sim[i][j] bitwise symmetric (same k-order both sides) — required.
// =====================================================================
__global__ void __launch_bounds__(256) k_sim() {
    __shared__ float A[32][65], Bm[32][65];
    const int b = blockIdx.z, i0 = blockIdx.y * 32, j0 = blockIdx.x * 32;
    const int tid = threadIdx.x;
#pragma unroll
    for (int it = 0; it < 2; it++) {
        int idx = tid + it * 256;
        int rr = idx >> 4, kk = (idx & 15) << 2;
        float4 v = *reinterpret_cast<const float4*>(
            &g_gu[((size_t)b * LL + i0 + rr) * GD + kk]);
        A[rr][kk] = v.x; A[rr][kk + 1] = v.y; A[rr][kk + 2] = v.z; A[rr][kk + 3] = v.w;
        float4 w = *reinterpret_cast<const float4*>(
            &g_gu[((size_t)b * LL + j0 + rr) * GD + kk]);
        Bm[rr][kk] = w.x; Bm[rr][kk + 1] = w.y; Bm[rr][kk + 2] = w.z; Bm[rr][kk + 3] = w.w;
    }
    __syncthreads();
    const int c = tid & 31, r0 = (tid >> 5) * 4;
    float acc[4] = {0.f, 0.f, 0.f, 0.f};
#pragma unroll
    for (int k = 0; k < GD; k++) {
        float bv = Bm[c][k];
#pragma unroll
        for (int u = 0; u < 4; u++) acc[u] = fmaf(A[r0 + u][k], bv, acc[u]);
    }
#pragma unroll
    for (int u = 0; u < 4; u++)
        g_sim[((size_t)b * LL + i0 + r0 + u) * LL + j0 + c] = acc[u];
}

// =====================================================================
// K3: per-row top-16 candidate keys (ascending). Warp per row.
// =====================================================================
__global__ void __launch_bounds__(256) k_lists() {
    const int warp = threadIdx.x >> 5, lane = threadIdx.x & 31;
    const int rr = blockIdx.x * 8 + warp;      // 0..4095 flattened
    const int r = rr & (LL - 1);
    const float4* row4 = reinterpret_cast<const float4*>(&g_sim[(size_t)rr * LL]);
    unsigned long long keys[16];
#pragma unroll
    for (int q = 0; q < 4; q++) {
        float4 v = row4[lane + q * 32];
        float f[4] = {v.x, v.y, v.z, v.w};
        int cbase = (lane + q * 32) * 4;
#pragma unroll
        for (int e = 0; e < 4; e++) {
            int cc = cbase + e;
            keys[q * 4 + e] = (cc == r) ? ~0ULL : mkkey(f[e], r, cc);
        }
    }
    unsigned long long* out = &g_lists[(size_t)rr * TL];
    for (int t = 0; t < TL; t++) {
        unsigned long long m = ~0ULL;
#pragma unroll
        for (int q = 0; q < 16; q++) m = keys[q] < m ? keys[q] : m;
#pragma unroll
        for (int o = 16; o; o >>= 1) {
            unsigned long long o2 = __shfl_xor_sync(0xffffffffu, m, o);
            m = o2 < m ? o2 : m;
        }
        if (lane == 0) out[t] = m;
#pragma unroll
        for (int q = 0; q < 16; q++) if (keys[q] == m) keys[q] = ~0ULL;
    }
}

// =====================================================================
// K4: greedy matching via iterated mutual-best rounds with smem top-16
// lists. One block per batch, 512 threads. Selected set identical to
// sequential greedy (distinct keys, lists hold true global top-16).
// =====================================================================
__global__ void __launch_bounds__(512) k_greedy() {
    extern __shared__ unsigned long long sl[];   // LL*TLP keys (69.6 KB)
    __shared__ unsigned long long best[LL];
    __shared__ unsigned char hd[LL];
    __shared__ unsigned used[16];
    __shared__ short qrows[LL];
    __shared__ int qn, nsel;
    __shared__ short sel_i[KK], sel_j[KK];
    __shared__ unsigned ibits[16];

    const int b = blockIdx.x, tid = threadIdx.x;
    const int warp = tid >> 5, lane = tid & 31;
    const float* simb = &g_sim[(size_t)b * LL * LL];

    // copy lists (stride-16 global -> stride-17 smem)
#pragma unroll
    for (int q = 0; q < TL; q++) {
        int idx = tid + q * 512;                 // 0..8191
        sl[(size_t)(idx >> 4) * TLP + (idx & 15)] = g_lists[(size_t)b * LL * TL + idx];
    }
    if (tid < 16) { used[tid] = 0u; ibits[tid] = 0u; }
    if (tid == 0) { nsel = 0; qn = 0; }
    __syncthreads();
    best[tid] = sl[(size_t)tid * TLP];
    hd[tid] = 1;
    __syncthreads();

    while (true) {
        // --- phase A: mutual-best selection (thread per row) ---
        {
            const int r = tid;
            if (!((used[r >> 5] >> (r & 31)) & 1u)) {
                unsigned long long k = best[r];
                int a = (int)((k >> 9) & 511), d = (int)(k & 511);
                if (r == a && best[d] == k) {    // mutual; select once at min endpoint
                    int s = atomicAdd(&nsel, 1);
                    sel_i[s] = (short)a; sel_j[s] = (short)d;
                    atomicOr(&used[a >> 5], 1u << (a & 31));
                    atomicOr(&used[d >> 5], 1u << (d & 31));
                }
            }
            if (tid == 0) qn = 0;
        }
        __syncthreads();
        if (nsel >= KK) break;

        // --- phase B: advance dead rows via smem list; queue exhausted ---
        {
            const int r = tid;
            if (!((used[r >> 5] >> (r & 31)) & 1u)) {
                unsigned long long k = best[r];
                int a = (int)((k >> 9) & 511), d = (int)(k & 511);
                int p = a ^ d ^ r;
                if ((used[p >> 5] >> (p & 31)) & 1u) {   // cached best died
                    int h = hd[r];
                    unsigned long long nb = ~0ULL;
                    while (h < TL) {
                        unsigned long long e = sl[(size_t)r * TLP + h]; h++;
                        int p2 = ((int)((e >> 9) & 511)) ^ ((int)(e & 511)) ^ r;
                        if (!((used[p2 >> 5] >> (p2 & 31)) & 1u)) { nb = e; break; }
                    }
                    hd[r] = (unsigned char)h;
                    if (nb != ~0ULL) best[r] = nb;
                    else qrows[atomicAdd(&qn, 1)] = (short)r;
                }
            }
        }
        __syncthreads();

        // --- phase C: warp-parallel full rescans (rare; L2-resident rows) ---
        for (int qi = warp; qi < qn; qi += 16) {
            const int r = qrows[qi];
            const float4* row4 = reinterpret_cast<const float4*>(&simb[(size_t)r * LL]);
            float4 v[4];
#pragma unroll
            for (int q = 0; q < 4; q++) v[q] = row4[lane + q * 32];
            unsigned long long m = ~0ULL;
#pragma unroll
            for (int q = 0; q < 4; q++) {
                float f[4] = {v[q].x, v[q].y, v[q].z, v[q].w};
                int cbase = (lane + q * 32) * 4;
#pragma unroll
                for (int e = 0; e < 4; e++) {
                    int cc = cbase + e;
                    if (cc == r) continue;
                    if ((used[cc >> 5] >> (cc & 31)) & 1u) continue;
                    unsigned long long kk = mkkey(f[e], r, cc);
                    m = kk < m ? kk : m;
                }
            }
#pragma unroll
            for (int o = 16; o; o >>= 1) {
                unsigned long long o2 = __shfl_xor_sync(0xffffffffu, m, o);
                m = o2 < m ? o2 : m;
            }
            if (lane == 0) best[r] = m;
        }
        __syncthreads();
    }

    // --- emit kept-slot pair records (rank = position of i among sorted i's) ---
    if (tid < KK) atomicOr(&ibits[sel_i[tid] >> 5], 1u << (sel_i[tid] & 31));
    __syncthreads();
    if (tid < KK) {
        int i = sel_i[tid], j = sel_j[tid];
        int rank = 0;
        for (int w2 = 0; w2 < (i >> 5); w2++) rank += __popc(ibits[w2]);
        rank += __popc(ibits[i >> 5] & ((1u << (i & 31)) - 1u));
        float wi = g_gn[b * LL + i], wj = g_gn[b * LL + j];
        g_pairs[b * KK + rank] = make_int4(i, j, __float_as_int(wi), __float_as_int(wj));
    }
}

// =====================================================================
// K5: merge outputs — xm then sm (HBM-bound, float4 everywhere)
// =====================================================================
__global__ void __launch_bounds__(256) k_merge(const float* __restrict__ x,
                                               const float* __restrict__ src,
                                               float* __restrict__ out) {
    const int blk = blockIdx.x;
    const int b = blk >> 8, slot = blk & 255;
    int4 p = g_pairs[blk];
    const int i = p.x, j = p.y;
    const float wi = __int_as_float(p.z), wj = __int_as_float(p.w);
    const float tot = wi + wj + 1e-8f;
    const float ai = wi / tot, aj = wj / tot;
    const int t = threadIdx.x;

    const float4* xi = reinterpret_cast<const float4*>(&x[((size_t)b * LL + i) * DD]);
    const float4* xj = reinterpret_cast<const float4*>(&x[((size_t)b * LL + j) * DD]);
    float4* xo = reinterpret_cast<float4*>(&out[((size_t)b * KK + slot) * DD]);
    {
        float4 a = xi[t], c = xj[t], o;
        o.x = fmaf(ai, a.x, aj * c.x);
        o.y = fmaf(ai, a.y, aj * c.y);
        o.z = fmaf(ai, a.z, aj * c.z);
        o.w = fmaf(ai, a.w, aj * c.w);
        xo[t] = o;
    }
    const float4* si = reinterpret_cast<const float4*>(&src[((size_t)b * LL + i) * NN]);
    const float4* sj = reinterpret_cast<const float4*>(&src[((size_t)b * LL + j) * NN]);
    float4* so = reinterpret_cast<float4*>(
        &out[(size_t)BB * KK * DD + ((size_t)b * KK + slot) * NN]);
#pragma unroll
    for (int q = 0; q < 8; q++) {
        int idx = t + q * 256;
        float4 a = si[idx], c = sj[idx], o;
        o.x = a.x + c.x; o.y = a.y + c.y; o.z = a.z + c.z; o.w = a.w + c.w;
        so[idx] = o;
    }
}

// =====================================================================
extern "C" void kernel_launch(void* const* d_in, const int* in_sizes, int n_in,
                              void* d_out, int out_size) {
    const float* x = nullptr;
    const float* src = nullptr;
    const float* W = nullptr;
    for (int k = 0; k < n_in; k++) {
        if (in_sizes[k] == BB * LL * DD) x = (const float*)d_in[k];
        else if (in_sizes[k] == BB * LL * NN) src = (const float*)d_in[k];
        else if (in_sizes[k] == GD * DD) W = (const float*)d_in[k];
    }
    float* out = (float*)d_out;

    cudaFuncSetAttribute(k_greedy, cudaFuncAttributeMaxDynamicSharedMemorySize,
                         LL * TLP * (int)sizeof(unsigned long long));

    k_proj<<<(BB * LL) / 32, 256>>>(x, W);
    dim3 gsim(16, 16, BB);
    k_sim<<<gsim, 256>>>();
    k_lists<<<(BB * LL) / 8, 256>>>();
    k_greedy<<<BB, 512, LL * TLP * sizeof(unsigned long long)>>>();
    k_merge<<<BB * KK, 256>>>(x, src, out);
}